// round 5
// baseline (speedup 1.0000x reference)
#include <cuda_runtime.h>
#include <cstdint>
#include <cstddef>

#define Mdim 256
#define Ndim 1024
#define Bdim 16384
#define Kiter 16
#define Pk 50u

// ---------------------------------------------------------------------------
// Scratch (allocation-free __device__ globals). Batch-major layout.
// All GEMM operands persisted as tf32 hi/lo pairs so the GEMM mainloop has
// zero cvt instructions.
// ---------------------------------------------------------------------------
__device__ float g_xhi [(size_t)Bdim * Ndim];
__device__ float g_xlo [(size_t)Bdim * Ndim];
__device__ float g_rhi [(size_t)Bdim * Mdim];
__device__ float g_rlo [(size_t)Bdim * Mdim];
__device__ float g_c   [(size_t)Bdim * Ndim];
__device__ float g_phihi[(size_t)Mdim * Ndim];   // phi (M,N) k=n contiguous
__device__ float g_philo[(size_t)Mdim * Ndim];
__device__ float g_wthi [(size_t)Ndim * Mdim];   // W^T (N,M) k=m contiguous
__device__ float g_wtlo [(size_t)Ndim * Mdim];

// ---------------------------------------------------------------------------
// PTX helpers (plain-sm_103-legal: cp.async sm_80+, mma.sync tf32 sm_80+)
// ---------------------------------------------------------------------------
__device__ __forceinline__ void cp_async16(uint32_t saddr, const void* gaddr) {
    asm volatile("cp.async.cg.shared.global [%0], [%1], 16;\n"
                 :: "r"(saddr), "l"(gaddr));
}
#define CP_COMMIT() asm volatile("cp.async.commit_group;\n" ::: "memory")
#define CP_WAIT0()  asm volatile("cp.async.wait_group 0;\n" ::: "memory")
#define CP_WAIT1()  asm volatile("cp.async.wait_group 1;\n" ::: "memory")

__device__ __forceinline__ void split_tf32(float v, float& hi, float& lo) {
    uint32_t h, l;
    asm("cvt.rna.tf32.f32 %0, %1;" : "=r"(h) : "f"(v));
    float hf = __uint_as_float(h);
    asm("cvt.rna.tf32.f32 %0, %1;" : "=r"(l) : "f"(v - hf));
    hi = hf;
    lo = __uint_as_float(l);
}

__device__ __forceinline__ void mma_tf32(float* d, const uint32_t* a,
                                         const uint32_t* b) {
    asm volatile(
        "mma.sync.aligned.m16n8k8.row.col.f32.tf32.tf32.f32 "
        "{%0,%1,%2,%3}, {%4,%5,%6,%7}, {%8,%9}, {%0,%1,%2,%3};"
        : "+f"(d[0]), "+f"(d[1]), "+f"(d[2]), "+f"(d[3])
        : "r"(a[0]), "r"(a[1]), "r"(a[2]), "r"(a[3]),
          "r"(b[0]), "r"(b[1]));
}

// ---------------------------------------------------------------------------
// TF32x3 GEMM (pre-split operands):
//   D(B x Nrows) = (Ahi+Alo)(B,Kd) @ (Bhi+Blo)(Nrows,Kd)^T  [- Sub if SPLIT_OUT]
// Tile 128(b) x 128(n) x 16(k), 256 threads (8 warps 2x4), warp tile 64x32.
// smem/stage: 4 operands x 128 rows x ROWPAD floats. Double-buffered.
// Mainloop: LDS + MMA only (no cvt).
// SPLIT_OUT=1: epilogue subtracts Sub (row stride CStride) and writes tf32
//              hi/lo split to Dhi/Dlo. SPLIT_OUT=0: plain fp32 store to Dhi.
// ---------------------------------------------------------------------------
#define KTILE 16
#define ROWPAD 20
#define OP_FLOATS (128 * ROWPAD)                 // 2560 floats per operand
#define STAGE_FLOATS (4 * OP_FLOATS)             // 10240
#define STAGE_BYTES (STAGE_FLOATS * 4)           // 40960 B
#define GEMM_SMEM (2 * STAGE_BYTES)              // 81920 B

template<int SPLIT_OUT>
__global__ void __launch_bounds__(256, 2)
gemm_tc(const float* __restrict__ Ahi, const float* __restrict__ Alo,
        const float* __restrict__ Bhi, const float* __restrict__ Blo,
        float* __restrict__ Dhi, float* __restrict__ Dlo,
        const float* __restrict__ Sub, int Kd, int CStride)
{
    extern __shared__ float sm[];
    const int tid  = threadIdx.x;
    const int wid  = tid >> 5;
    const int lane = tid & 31;
    const int gid  = lane >> 2;
    const int tig  = lane & 3;
    const int wm   = wid >> 2;       // 0..1 -> 64-row strip
    const int wn   = wid & 3;        // 0..3 -> 32-col strip
    const int b0   = blockIdx.y * 128;
    const int n0   = blockIdx.x * 128;
    const uint32_t smbase = (uint32_t)__cvta_generic_to_shared(sm);

    float acc[4][4][4];
#pragma unroll
    for (int i = 0; i < 4; i++)
#pragma unroll
        for (int j = 0; j < 4; j++)
#pragma unroll
            for (int q = 0; q < 4; q++) acc[i][j][q] = 0.0f;

    // 4 operands x 128 rows x 4 chunks(16B) = 2048 chunks; 8 per thread
    auto load_stage = [&](int t, int buf) {
        const int k0 = t * KTILE;
        const uint32_t sb = smbase + buf * STAGE_BYTES;
#pragma unroll
        for (int l = 0; l < 8; l++) {
            int idx = tid + l * 256;             // 0..2047
            int op  = idx >> 9;                  // 0..3: Ahi Alo Bhi Blo
            int rem = idx & 511;
            int row = rem >> 2;                  // 0..127
            int ch  = rem & 3;                   // 0..3
            const float* src;
            if (op == 0)      src = Ahi + (size_t)(b0 + row) * Kd;
            else if (op == 1) src = Alo + (size_t)(b0 + row) * Kd;
            else if (op == 2) src = Bhi + (size_t)(n0 + row) * Kd;
            else              src = Blo + (size_t)(n0 + row) * Kd;
            cp_async16(sb + (op * OP_FLOATS + row * ROWPAD + ch * 4) * 4,
                       src + k0 + ch * 4);
        }
    };

    const int T = Kd / KTILE;
    load_stage(0, 0);
    CP_COMMIT();

    for (int t = 0; t < T; t++) {
        const int buf = t & 1;
        if (t + 1 < T) {
            load_stage(t + 1, buf ^ 1);
            CP_COMMIT();
            CP_WAIT1();
        } else {
            CP_WAIT0();
        }
        __syncthreads();

        const float* Ah = sm + buf * STAGE_FLOATS;
        const float* Al = Ah + OP_FLOATS;
        const float* Bh = Al + OP_FLOATS;
        const float* Bl = Bh + OP_FLOATS;

#pragma unroll
        for (int s = 0; s < 2; s++) {
            const int kb = s * 8;
            uint32_t bhi[4][2], blo[4][2];
#pragma unroll
            for (int nt = 0; nt < 4; nt++) {
                int n = wn * 32 + nt * 8 + gid;
                bhi[nt][0] = __float_as_uint(Bh[n * ROWPAD + kb + tig]);
                bhi[nt][1] = __float_as_uint(Bh[n * ROWPAD + kb + tig + 4]);
                blo[nt][0] = __float_as_uint(Bl[n * ROWPAD + kb + tig]);
                blo[nt][1] = __float_as_uint(Bl[n * ROWPAD + kb + tig + 4]);
            }
#pragma unroll
            for (int mt = 0; mt < 4; mt++) {
                int m = wm * 64 + mt * 16 + gid;
                uint32_t ahi[4], alo[4];
                ahi[0] = __float_as_uint(Ah[m * ROWPAD + kb + tig]);
                ahi[1] = __float_as_uint(Ah[(m + 8) * ROWPAD + kb + tig]);
                ahi[2] = __float_as_uint(Ah[m * ROWPAD + kb + tig + 4]);
                ahi[3] = __float_as_uint(Ah[(m + 8) * ROWPAD + kb + tig + 4]);
                alo[0] = __float_as_uint(Al[m * ROWPAD + kb + tig]);
                alo[1] = __float_as_uint(Al[(m + 8) * ROWPAD + kb + tig]);
                alo[2] = __float_as_uint(Al[m * ROWPAD + kb + tig + 4]);
                alo[3] = __float_as_uint(Al[(m + 8) * ROWPAD + kb + tig + 4]);
#pragma unroll
                for (int nt = 0; nt < 4; nt++) {
                    mma_tf32(acc[mt][nt], ahi, bhi[nt]);
                    mma_tf32(acc[mt][nt], ahi, blo[nt]);
                    mma_tf32(acc[mt][nt], alo, bhi[nt]);
                }
            }
        }
        __syncthreads();
    }

    // Epilogue. Fragment: c0:(r,2c) c1:(r,2c+1) c2:(r+8,2c) c3:(r+8,2c+1)
#pragma unroll
    for (int mt = 0; mt < 4; mt++) {
        int r0 = b0 + wm * 64 + mt * 16 + gid;
#pragma unroll
        for (int nt = 0; nt < 4; nt++) {
            int col = n0 + wn * 32 + nt * 8 + tig * 2;
#pragma unroll
            for (int half = 0; half < 2; half++) {
                int rr = r0 + half * 8;
                float2 v = make_float2(acc[mt][nt][half * 2],
                                       acc[mt][nt][half * 2 + 1]);
                size_t o = (size_t)rr * CStride + col;
                if (SPLIT_OUT) {
                    float2 yv = *(const float2*)(Sub + o);
                    v.x -= yv.x;
                    v.y -= yv.y;
                    float2 h, l;
                    split_tf32(v.x, h.x, l.x);
                    split_tf32(v.y, h.y, l.y);
                    *(float2*)(Dhi + o) = h;
                    *(float2*)(Dlo + o) = l;
                } else {
                    *(float2*)(Dhi + o) = v;
                }
            }
        }
    }
}

// ---------------------------------------------------------------------------
// Fused update on (B,N): one warp per batch row.
// x = xhi + xlo; v = x - gamma*c; thr = exact Pk-th largest |v| (4-pass radix
// select on fp32 bits); res = (|v|>thr) ? v : soft(v, theta*g(|x|)).
// LAST=0: write tf32 split back to xhi/xlo.  LAST=1: write fp32 to outp.
// ---------------------------------------------------------------------------
template<int LAST>
__global__ void __launch_bounds__(256)
update_kernel(float* __restrict__ xhi, float* __restrict__ xlo,
              const float* __restrict__ c, float* __restrict__ outp,
              const float* __restrict__ gammaArr,
              const float* __restrict__ thetaArr, int it)
{
    __shared__ float    v[8][1024];
    __shared__ unsigned hist[8][256];

    const int tid  = threadIdx.x;
    const int w    = tid >> 5;
    const int lane = tid & 31;
    const size_t base = ((size_t)blockIdx.x * 8 + w) * Ndim;
    const float gamma = gammaArr[it];
    const float theta = thetaArr[it];

    float xabs[32];
#pragma unroll
    for (int i = 0; i < 8; i++) {
        int n = i * 128 + lane * 4;
        float4 xh = *(const float4*)(xhi + base + n);
        float4 xl = *(const float4*)(xlo + base + n);
        float4 cc = *(const float4*)(c + base + n);
        float x0 = xh.x + xl.x, x1 = xh.y + xl.y;
        float x2 = xh.z + xl.z, x3 = xh.w + xl.w;
        xabs[i * 4 + 0] = fabsf(x0);
        xabs[i * 4 + 1] = fabsf(x1);
        xabs[i * 4 + 2] = fabsf(x2);
        xabs[i * 4 + 3] = fabsf(x3);
        float4 vv;
        vv.x = x0 - gamma * cc.x;
        vv.y = x1 - gamma * cc.y;
        vv.z = x2 - gamma * cc.z;
        vv.w = x3 - gamma * cc.w;
        *(float4*)(&v[w][n]) = vv;
    }
    __syncwarp();

    // exact radix select of Pk-th largest |v| over 1024 values
    unsigned prefix = 0u, mask = 0u, k = Pk;
    unsigned* h = hist[w];
#pragma unroll
    for (int pass = 0; pass < 4; pass++) {
        const int shift = 24 - 8 * pass;
#pragma unroll
        for (int i = lane; i < 256; i += 32) h[i] = 0u;
        __syncwarp();
        for (int n = lane; n < 1024; n += 32) {
            unsigned e = __float_as_uint(v[w][n]) & 0x7FFFFFFFu;
            if ((e & mask) == prefix)
                atomicAdd(&h[(e >> shift) & 0xFFu], 1u);
        }
        __syncwarp();
        unsigned loc[8];
        unsigned s = 0u;
#pragma unroll
        for (int r = 7; r >= 0; r--) { s += h[lane * 8 + r]; loc[r] = s; }
        unsigned inc = s;
#pragma unroll
        for (int off = 1; off < 32; off <<= 1) {
            unsigned t = __shfl_down_sync(0xffffffffu, inc, off);
            if (lane + off < 32) inc += t;
        }
        const unsigned above = inc - s;
        unsigned dfound = 0u, kfound = 0u;
        bool found = false;
#pragma unroll
        for (int r = 7; r >= 0; r--) {
            unsigned cge  = above + loc[r];
            unsigned cge1 = above + (r < 7 ? loc[r + 1] : 0u);
            if (cge >= k && cge1 < k) {
                dfound = (unsigned)(lane * 8 + r);
                kfound = k - cge1;
                found = true;
            }
        }
        unsigned bal = __ballot_sync(0xffffffffu, found);
        int src = __ffs(bal) - 1;
        dfound = __shfl_sync(0xffffffffu, dfound, src);
        kfound = __shfl_sync(0xffffffffu, kfound, src);
        k = kfound;
        prefix |= dfound << shift;
        mask   |= 0xFFu << shift;
        __syncwarp();
    }
    const float thrv = __uint_as_float(prefix);

#pragma unroll
    for (int i = 0; i < 8; i++) {
        int n = i * 128 + lane * 4;
        float4 vv = *(const float4*)(&v[w][n]);
        float res[4];
        const float* vp = &vv.x;
#pragma unroll
        for (int jc = 0; jc < 4; jc++) {
            float val = vp[jc];
            float av = fabsf(val);
            float th = theta * (1.0f / (xabs[i * 4 + jc] / 0.1f + 1.0f));
            float st = copysignf(fmaxf(av - th, 0.0f), val);
            res[jc] = (av > thrv) ? val : st;
        }
        if (LAST) {
            *(float4*)(outp + base + n) = make_float4(res[0], res[1], res[2], res[3]);
        } else {
            float4 hq, lq;
            split_tf32(res[0], hq.x, lq.x);
            split_tf32(res[1], hq.y, lq.y);
            split_tf32(res[2], hq.z, lq.z);
            split_tf32(res[3], hq.w, lq.w);
            *(float4*)(xhi + base + n) = hq;
            *(float4*)(xlo + base + n) = lq;
        }
    }
}

// ---------------------------------------------------------------------------
// Prep / misc kernels
// ---------------------------------------------------------------------------
__global__ void split_kernel(const float* __restrict__ in, float* __restrict__ hi,
                             float* __restrict__ lo, size_t n)
{
    for (size_t i = (size_t)blockIdx.x * blockDim.x + threadIdx.x; i < n;
         i += (size_t)gridDim.x * blockDim.x) {
        float h, l;
        split_tf32(in[i], h, l);
        hi[i] = h;
        lo[i] = l;
    }
}

__global__ void neg_split_kernel(const float* __restrict__ in,
                                 float* __restrict__ hi, float* __restrict__ lo,
                                 size_t n)
{
    for (size_t i = (size_t)blockIdx.x * blockDim.x + threadIdx.x; i < n;
         i += (size_t)gridDim.x * blockDim.x) {
        float h, l;
        split_tf32(-in[i], h, l);
        hi[i] = h;
        lo[i] = l;
    }
}

__global__ void transpose_split_kernel(const float* __restrict__ W,
                                       float* __restrict__ wthi,
                                       float* __restrict__ wtlo)
{
    __shared__ float tile[32][33];
    int n0 = blockIdx.x * 32;
    int m0 = blockIdx.y * 32;
    int tx = threadIdx.x, ty = threadIdx.y;
    for (int i = ty; i < 32; i += 8)
        tile[i][tx] = W[(size_t)(m0 + i) * Ndim + n0 + tx];
    __syncthreads();
    for (int i = ty; i < 32; i += 8) {
        float h, l;
        split_tf32(tile[tx][i], h, l);
        size_t o = (size_t)(n0 + i) * Mdim + m0 + tx;
        wthi[o] = h;
        wtlo[o] = l;
    }
}

__global__ void zero_kernel(float* __restrict__ p, size_t n)
{
    for (size_t i = (size_t)blockIdx.x * blockDim.x + threadIdx.x; i < n;
         i += (size_t)gridDim.x * blockDim.x)
        p[i] = 0.0f;
}

// ---------------------------------------------------------------------------
// Launch
// ---------------------------------------------------------------------------
extern "C" void kernel_launch(void* const* d_in, const int* in_sizes, int n_in,
                              void* d_out, int out_size)
{
    const float* y     = (const float*)d_in[0];
    const float* phi   = (const float*)d_in[1];
    const float* W     = (const float*)d_in[2];
    const float* gamma = (const float*)d_in[3];
    const float* theta = (const float*)d_in[4];
    float* out = (float*)d_out;

    float *xhi, *xlo, *rhi, *rlo, *cp, *phihi, *philo, *wthi, *wtlo;
    cudaGetSymbolAddress((void**)&xhi,   g_xhi);
    cudaGetSymbolAddress((void**)&xlo,   g_xlo);
    cudaGetSymbolAddress((void**)&rhi,   g_rhi);
    cudaGetSymbolAddress((void**)&rlo,   g_rlo);
    cudaGetSymbolAddress((void**)&cp,    g_c);
    cudaGetSymbolAddress((void**)&phihi, g_phihi);
    cudaGetSymbolAddress((void**)&philo, g_philo);
    cudaGetSymbolAddress((void**)&wthi,  g_wthi);
    cudaGetSymbolAddress((void**)&wtlo,  g_wtlo);

    cudaFuncSetAttribute(gemm_tc<1>, cudaFuncAttributeMaxDynamicSharedMemorySize,
                         GEMM_SMEM);
    cudaFuncSetAttribute(gemm_tc<0>, cudaFuncAttributeMaxDynamicSharedMemorySize,
                         GEMM_SMEM);

    split_kernel<<<512, 256>>>(phi, phihi, philo, (size_t)Mdim * Ndim);
    transpose_split_kernel<<<dim3(Ndim / 32, Mdim / 32), dim3(32, 8)>>>(W, wthi, wtlo);
    zero_kernel<<<2048, 256>>>(xhi, (size_t)Bdim * Ndim);
    zero_kernel<<<2048, 256>>>(xlo, (size_t)Bdim * Ndim);

    for (int it = 0; it < Kiter; it++) {
        // r = x @ phi^T - y (split output). it 0: x=0 -> r = -y.
        if (it == 0) {
            neg_split_kernel<<<2048, 256>>>(y, rhi, rlo, (size_t)Bdim * Mdim);
        } else {
            gemm_tc<1><<<dim3(Mdim / 128, Bdim / 128), 256, GEMM_SMEM>>>(
                xhi, xlo, phihi, philo, rhi, rlo, y, Ndim, Mdim);
        }
        // c = r @ W  (B operand = W^T, k-major over M)
        gemm_tc<0><<<dim3(Ndim / 128, Bdim / 128), 256, GEMM_SMEM>>>(
            rhi, rlo, wthi, wtlo, cp, nullptr, nullptr, Mdim, Ndim);
        // x = soft_threshold(x - gamma*c, theta*g(|x|), 50)
        if (it == Kiter - 1)
            update_kernel<1><<<Bdim / 8, 256>>>(xhi, xlo, cp, out, gamma, theta, it);
        else
            update_kernel<0><<<Bdim / 8, 256>>>(xhi, xlo, cp, nullptr, gamma, theta, it);
    }

    // zero the tail (the two (K,1) zero outputs appended after x)
    long long tail = (long long)out_size - (long long)Ndim * Bdim;
    if (tail > 0)
        zero_kernel<<<1, 256>>>(out + (size_t)Ndim * Bdim, (size_t)tail);
}

// round 7
// speedup vs baseline: 1.0438x; 1.0438x over previous
#include <cuda_runtime.h>
#include <cstdint>
#include <cstddef>

#define Mdim 256
#define Ndim 1024
#define Bdim 16384
#define Kiter 16
#define Pk 50u

// ---------------------------------------------------------------------------
// Scratch (allocation-free __device__ globals). Batch-major layout.
// Big tensors fp32; small constant matrices pre-split into tf32 hi/lo.
// ---------------------------------------------------------------------------
__device__ float g_x [(size_t)Bdim * Ndim];      // x (B,N)
__device__ float g_r [(size_t)Bdim * Mdim];      // r (B,M)
__device__ float g_c [(size_t)Bdim * Ndim];      // c (B,N)
__device__ float g_phihi[(size_t)Mdim * Ndim];   // phi (M,N), k=n contiguous
__device__ float g_philo[(size_t)Mdim * Ndim];
__device__ float g_wthi [(size_t)Ndim * Mdim];   // W^T (N,M), k=m contiguous
__device__ float g_wtlo [(size_t)Ndim * Mdim];

// ---------------------------------------------------------------------------
// PTX helpers (plain-sm_103-legal: cp.async sm_80+, mma.sync tf32 sm_80+)
// ---------------------------------------------------------------------------
__device__ __forceinline__ void cp_async16(uint32_t saddr, const void* gaddr) {
    asm volatile("cp.async.cg.shared.global [%0], [%1], 16;\n"
                 :: "r"(saddr), "l"(gaddr));
}
#define CP_COMMIT() asm volatile("cp.async.commit_group;\n" ::: "memory")
#define CP_WAIT0()  asm volatile("cp.async.wait_group 0;\n" ::: "memory")
#define CP_WAIT1()  asm volatile("cp.async.wait_group 1;\n" ::: "memory")

__device__ __forceinline__ void split_tf32(float v, float& hi, float& lo) {
    uint32_t h, l;
    asm("cvt.rna.tf32.f32 %0, %1;" : "=r"(h) : "f"(v));
    float hf = __uint_as_float(h);
    asm("cvt.rna.tf32.f32 %0, %1;" : "=r"(l) : "f"(v - hf));
    hi = hf;
    lo = __uint_as_float(l);
}

__device__ __forceinline__ void mma_tf32(float* d, const uint32_t* a,
                                         const uint32_t* b) {
    asm volatile(
        "mma.sync.aligned.m16n8k8.row.col.f32.tf32.tf32.f32 "
        "{%0,%1,%2,%3}, {%4,%5,%6,%7}, {%8,%9}, {%0,%1,%2,%3};"
        : "+f"(d[0]), "+f"(d[1]), "+f"(d[2]), "+f"(d[3])
        : "r"(a[0]), "r"(a[1]), "r"(a[2]), "r"(a[3]),
          "r"(b[0]), "r"(b[1]));
}

// ---------------------------------------------------------------------------
// TF32x3 GEMM:  D(B x Nrows) = A(B,Kd) @ (Bhi+Blo)(Nrows,Kd)^T  [- Sub if SUBY]
// A fp32 in global -> cp.async staging -> cooperative split to Ahi/Alo smem
// (once per element). B pre-split in global. Mainloop: LDS + MMA only.
// Tile 128(b) x 128(n) x 16(k), 256 threads (8 warps 2x4), warp tile 64x32.
// Sync protocol per tile: [cp visible] -> split -> [split visible] -> MMA ->
// [MMA done]  (3rd barrier protects the double buffers from next-iter cp.async)
// ---------------------------------------------------------------------------
#define KTILE 16
#define ROWPAD 20
#define OPF (128 * ROWPAD)           // 2560 floats per operand tile
// smem floats: staging[2]  Ahi  Alo  Bhi[2]  Blo[2]  = 8 * OPF
#define OFF_STG  0
#define OFF_AHI  (2 * OPF)
#define OFF_ALO  (3 * OPF)
#define OFF_BHI  (4 * OPF)
#define OFF_BLO  (6 * OPF)
#define GEMM_SMEM (8 * OPF * 4)      // 81920 B

template<int SUBY>
__global__ void __launch_bounds__(256, 2)
gemm_tc(const float* __restrict__ A,
        const float* __restrict__ Bhi, const float* __restrict__ Blo,
        float* __restrict__ D, const float* __restrict__ Sub,
        int Kd, int CStride)
{
    extern __shared__ float sm[];
    const int tid  = threadIdx.x;
    const int wid  = tid >> 5;
    const int lane = tid & 31;
    const int gid  = lane >> 2;
    const int tig  = lane & 3;
    const int wm   = wid >> 2;       // 0..1 -> 64-row strip (batch)
    const int wn   = wid & 3;        // 0..3 -> 32-col strip (n)
    const int b0   = blockIdx.y * 128;
    const int n0   = blockIdx.x * 128;
    const uint32_t smbase = (uint32_t)__cvta_generic_to_shared(sm);

    float acc[4][4][4];
#pragma unroll
    for (int i = 0; i < 4; i++)
#pragma unroll
        for (int j = 0; j < 4; j++)
#pragma unroll
            for (int q = 0; q < 4; q++) acc[i][j][q] = 0.0f;

    // Stage loader: A fp32 512 chunks, Bhi 512, Blo 512 (16B each); 6/thread.
    auto load_stage = [&](int t, int buf) {
        const int k0 = t * KTILE;
        const uint32_t sA  = smbase + (OFF_STG + buf * OPF) * 4;
        const uint32_t sBh = smbase + (OFF_BHI + buf * OPF) * 4;
        const uint32_t sBl = smbase + (OFF_BLO + buf * OPF) * 4;
#pragma unroll
        for (int l = 0; l < 2; l++) {
            int idx = tid + l * 256;           // 0..511
            int row = idx >> 2;                // 0..127
            int ch  = idx & 3;                 // 0..3
            uint32_t so = (row * ROWPAD + ch * 4) * 4;
            cp_async16(sA + so, A + (size_t)(b0 + row) * Kd + k0 + ch * 4);
            cp_async16(sBh + so, Bhi + (size_t)(n0 + row) * Kd + k0 + ch * 4);
            cp_async16(sBl + so, Blo + (size_t)(n0 + row) * Kd + k0 + ch * 4);
        }
    };

    const int T = Kd / KTILE;
    load_stage(0, 0);
    CP_COMMIT();

    for (int t = 0; t < T; t++) {
        const int buf = t & 1;
        if (t + 1 < T) {
            load_stage(t + 1, buf ^ 1);
            CP_COMMIT();
            CP_WAIT1();
        } else {
            CP_WAIT0();
        }
        __syncthreads();   // cp(t) visible

        // Cooperative split: 8 floats per thread (staging -> Ahi/Alo)
        {
            const float* stg = sm + OFF_STG + buf * OPF;
            float* ahs = sm + OFF_AHI;
            float* als = sm + OFF_ALO;
            int row  = tid >> 1;
            int half = tid & 1;
            int o = row * ROWPAD + half * 8;
            float4 v0 = *(const float4*)(stg + o);
            float4 v1 = *(const float4*)(stg + o + 4);
            float4 h0, l0, h1, l1;
            split_tf32(v0.x, h0.x, l0.x); split_tf32(v0.y, h0.y, l0.y);
            split_tf32(v0.z, h0.z, l0.z); split_tf32(v0.w, h0.w, l0.w);
            split_tf32(v1.x, h1.x, l1.x); split_tf32(v1.y, h1.y, l1.y);
            split_tf32(v1.z, h1.z, l1.z); split_tf32(v1.w, h1.w, l1.w);
            *(float4*)(ahs + o) = h0; *(float4*)(ahs + o + 4) = h1;
            *(float4*)(als + o) = l0; *(float4*)(als + o + 4) = l1;
        }
        __syncthreads();   // split visible

        const float* Ah = sm + OFF_AHI;
        const float* Al = sm + OFF_ALO;
        const float* Bh = sm + OFF_BHI + buf * OPF;
        const float* Bl = sm + OFF_BLO + buf * OPF;

#pragma unroll
        for (int s = 0; s < 2; s++) {
            const int kb = s * 8;
            uint32_t bhi[4][2], blo[4][2];
#pragma unroll
            for (int nt = 0; nt < 4; nt++) {
                int n = wn * 32 + nt * 8 + gid;
                bhi[nt][0] = __float_as_uint(Bh[n * ROWPAD + kb + tig]);
                bhi[nt][1] = __float_as_uint(Bh[n * ROWPAD + kb + tig + 4]);
                blo[nt][0] = __float_as_uint(Bl[n * ROWPAD + kb + tig]);
                blo[nt][1] = __float_as_uint(Bl[n * ROWPAD + kb + tig + 4]);
            }
#pragma unroll
            for (int mt = 0; mt < 4; mt++) {
                int m = wm * 64 + mt * 16 + gid;
                uint32_t ahi[4], alo[4];
                ahi[0] = __float_as_uint(Ah[m * ROWPAD + kb + tig]);
                ahi[1] = __float_as_uint(Ah[(m + 8) * ROWPAD + kb + tig]);
                ahi[2] = __float_as_uint(Ah[m * ROWPAD + kb + tig + 4]);
                ahi[3] = __float_as_uint(Ah[(m + 8) * ROWPAD + kb + tig + 4]);
                alo[0] = __float_as_uint(Al[m * ROWPAD + kb + tig]);
                alo[1] = __float_as_uint(Al[(m + 8) * ROWPAD + kb + tig]);
                alo[2] = __float_as_uint(Al[m * ROWPAD + kb + tig + 4]);
                alo[3] = __float_as_uint(Al[(m + 8) * ROWPAD + kb + tig + 4]);
#pragma unroll
                for (int nt = 0; nt < 4; nt++) {
                    mma_tf32(acc[mt][nt], ahi, bhi[nt]);
                    mma_tf32(acc[mt][nt], ahi, blo[nt]);
                    mma_tf32(acc[mt][nt], alo, bhi[nt]);
                }
            }
        }
        __syncthreads();   // MMA(t) done — buffers safe for next-iter cp.async
    }

    // Epilogue. Fragment: c0:(r,2c) c1:(r,2c+1) c2:(r+8,2c) c3:(r+8,2c+1)
#pragma unroll
    for (int mt = 0; mt < 4; mt++) {
        int r0 = b0 + wm * 64 + mt * 16 + gid;
#pragma unroll
        for (int nt = 0; nt < 4; nt++) {
            int col = n0 + wn * 32 + nt * 8 + tig * 2;
#pragma unroll
            for (int half = 0; half < 2; half++) {
                int rr = r0 + half * 8;
                float2 v = make_float2(acc[mt][nt][half * 2],
                                       acc[mt][nt][half * 2 + 1]);
                size_t o = (size_t)rr * CStride + col;
                if (SUBY) {
                    float2 yv = *(const float2*)(Sub + o);
                    v.x -= yv.x;
                    v.y -= yv.y;
                }
                *(float2*)(D + o) = v;
            }
        }
    }
}

// ---------------------------------------------------------------------------
// Fused update on (B,N): one warp per batch row.
// v = x - gamma*c; thr = exact Pk-th largest |v| (4-pass radix select on fp32
// bits); xout = (|v|>thr) ? v : soft(v, theta*g(|x|)).
// ---------------------------------------------------------------------------
__global__ void __launch_bounds__(256)
update_kernel(const float* __restrict__ x, float* __restrict__ xout,
              const float* __restrict__ c,
              const float* __restrict__ gammaArr,
              const float* __restrict__ thetaArr, int it)
{
    __shared__ float    v[8][1024];
    __shared__ unsigned hist[8][256];

    const int tid  = threadIdx.x;
    const int w    = tid >> 5;
    const int lane = tid & 31;
    const size_t base = ((size_t)blockIdx.x * 8 + w) * Ndim;
    const float gamma = gammaArr[it];
    const float theta = thetaArr[it];

    float xabs[32];
#pragma unroll
    for (int i = 0; i < 8; i++) {
        int n = i * 128 + lane * 4;
        float4 xv = *(const float4*)(x + base + n);
        float4 cc = *(const float4*)(c + base + n);
        xabs[i * 4 + 0] = fabsf(xv.x);
        xabs[i * 4 + 1] = fabsf(xv.y);
        xabs[i * 4 + 2] = fabsf(xv.z);
        xabs[i * 4 + 3] = fabsf(xv.w);
        float4 vv;
        vv.x = xv.x - gamma * cc.x;
        vv.y = xv.y - gamma * cc.y;
        vv.z = xv.z - gamma * cc.z;
        vv.w = xv.w - gamma * cc.w;
        *(float4*)(&v[w][n]) = vv;
    }
    __syncwarp();

    // exact radix select of Pk-th largest |v| over 1024 values
    unsigned prefix = 0u, mask = 0u, k = Pk;
    unsigned* h = hist[w];
#pragma unroll
    for (int pass = 0; pass < 4; pass++) {
        const int shift = 24 - 8 * pass;
#pragma unroll
        for (int i = lane; i < 256; i += 32) h[i] = 0u;
        __syncwarp();
        for (int n = lane; n < 1024; n += 32) {
            unsigned e = __float_as_uint(v[w][n]) & 0x7FFFFFFFu;
            if ((e & mask) == prefix)
                atomicAdd(&h[(e >> shift) & 0xFFu], 1u);
        }
        __syncwarp();
        unsigned loc[8];
        unsigned s = 0u;
#pragma unroll
        for (int r = 7; r >= 0; r--) { s += h[lane * 8 + r]; loc[r] = s; }
        unsigned inc = s;
#pragma unroll
        for (int off = 1; off < 32; off <<= 1) {
            unsigned t = __shfl_down_sync(0xffffffffu, inc, off);
            if (lane + off < 32) inc += t;
        }
        const unsigned above = inc - s;
        unsigned dfound = 0u, kfound = 0u;
        bool found = false;
#pragma unroll
        for (int r = 7; r >= 0; r--) {
            unsigned cge  = above + loc[r];
            unsigned cge1 = above + (r < 7 ? loc[r + 1] : 0u);
            if (cge >= k && cge1 < k) {
                dfound = (unsigned)(lane * 8 + r);
                kfound = k - cge1;
                found = true;
            }
        }
        unsigned bal = __ballot_sync(0xffffffffu, found);
        int src = __ffs(bal) - 1;
        dfound = __shfl_sync(0xffffffffu, dfound, src);
        kfound = __shfl_sync(0xffffffffu, kfound, src);
        k = kfound;
        prefix |= dfound << shift;
        mask   |= 0xFFu << shift;
        __syncwarp();
    }
    const float thrv = __uint_as_float(prefix);

#pragma unroll
    for (int i = 0; i < 8; i++) {
        int n = i * 128 + lane * 4;
        float4 vv = *(const float4*)(&v[w][n]);
        float4 o;
        float* vp = &vv.x;
        float* op = &o.x;
#pragma unroll
        for (int jc = 0; jc < 4; jc++) {
            float val = vp[jc];
            float av = fabsf(val);
            float th = theta * (1.0f / (xabs[i * 4 + jc] / 0.1f + 1.0f));
            float st = copysignf(fmaxf(av - th, 0.0f), val);
            op[jc] = (av > thrv) ? val : st;
        }
        *(float4*)(xout + base + n) = o;
    }
}

// ---------------------------------------------------------------------------
// Prep / misc kernels
// ---------------------------------------------------------------------------
__global__ void split_kernel(const float* __restrict__ in, float* __restrict__ hi,
                             float* __restrict__ lo, size_t n)
{
    for (size_t i = (size_t)blockIdx.x * blockDim.x + threadIdx.x; i < n;
         i += (size_t)gridDim.x * blockDim.x) {
        float h, l;
        split_tf32(in[i], h, l);
        hi[i] = h;
        lo[i] = l;
    }
}

__global__ void transpose_split_kernel(const float* __restrict__ W,
                                       float* __restrict__ wthi,
                                       float* __restrict__ wtlo)
{
    __shared__ float tile[32][33];
    int n0 = blockIdx.x * 32;
    int m0 = blockIdx.y * 32;
    int tx = threadIdx.x, ty = threadIdx.y;
    for (int i = ty; i < 32; i += 8)
        tile[i][tx] = W[(size_t)(m0 + i) * Ndim + n0 + tx];
    __syncthreads();
    for (int i = ty; i < 32; i += 8) {
        float h, l;
        split_tf32(tile[tx][i], h, l);
        size_t o = (size_t)(n0 + i) * Mdim + m0 + tx;
        wthi[o] = h;
        wtlo[o] = l;
    }
}

__global__ void neg_copy_kernel(const float* __restrict__ src,
                                float* __restrict__ dst, size_t n)
{
    size_t i = ((size_t)blockIdx.x * blockDim.x + threadIdx.x) * 4;
    if (i < n) {
        float4 v = *(const float4*)(src + i);
        v.x = -v.x; v.y = -v.y; v.z = -v.z; v.w = -v.w;
        *(float4*)(dst + i) = v;
    }
}

__global__ void zero_kernel(float* __restrict__ p, size_t n)
{
    for (size_t i = (size_t)blockIdx.x * blockDim.x + threadIdx.x; i < n;
         i += (size_t)gridDim.x * blockDim.x)
        p[i] = 0.0f;
}

// ---------------------------------------------------------------------------
// Launch
// ---------------------------------------------------------------------------
extern "C" void kernel_launch(void* const* d_in, const int* in_sizes, int n_in,
                              void* d_out, int out_size)
{
    const float* y     = (const float*)d_in[0];
    const float* phi   = (const float*)d_in[1];
    const float* W     = (const float*)d_in[2];
    const float* gamma = (const float*)d_in[3];
    const float* theta = (const float*)d_in[4];
    float* out = (float*)d_out;

    float *xp, *rp, *cp, *phihi, *philo, *wthi, *wtlo;
    cudaGetSymbolAddress((void**)&xp,    g_x);
    cudaGetSymbolAddress((void**)&rp,    g_r);
    cudaGetSymbolAddress((void**)&cp,    g_c);
    cudaGetSymbolAddress((void**)&phihi, g_phihi);
    cudaGetSymbolAddress((void**)&philo, g_philo);
    cudaGetSymbolAddress((void**)&wthi,  g_wthi);
    cudaGetSymbolAddress((void**)&wtlo,  g_wtlo);

    cudaFuncSetAttribute(gemm_tc<1>, cudaFuncAttributeMaxDynamicSharedMemorySize,
                         GEMM_SMEM);
    cudaFuncSetAttribute(gemm_tc<0>, cudaFuncAttributeMaxDynamicSharedMemorySize,
                         GEMM_SMEM);

    split_kernel<<<512, 256>>>(phi, phihi, philo, (size_t)Mdim * Ndim);
    transpose_split_kernel<<<dim3(Ndim / 32, Mdim / 32), dim3(32, 8)>>>(W, wthi, wtlo);
    zero_kernel<<<2048, 256>>>(xp, (size_t)Bdim * Ndim);

    for (int it = 0; it < Kiter; it++) {
        // r = x @ phi^T - y  (it 0: x = 0 -> r = -y)
        if (it == 0) {
            neg_copy_kernel<<<(Bdim * Mdim / 4 + 255) / 256, 256>>>(
                y, rp, (size_t)Bdim * Mdim);
        } else {
            gemm_tc<1><<<dim3(Mdim / 128, Bdim / 128), 256, GEMM_SMEM>>>(
                xp, phihi, philo, rp, y, Ndim, Mdim);
        }
        // c = r @ W  (B operand = W^T, k-major over M)
        gemm_tc<0><<<dim3(Ndim / 128, Bdim / 128), 256, GEMM_SMEM>>>(
            rp, wthi, wtlo, cp, nullptr, Mdim, Ndim);
        // x = soft_threshold(x - gamma*c, theta*g(|x|), 50)
        float* xout = (it == Kiter - 1) ? out : xp;
        update_kernel<<<Bdim / 8, 256>>>(xp, xout, cp, gamma, theta, it);
    }

    // zero the tail (the two (K,1) zero outputs appended after x)
    long long tail = (long long)out_size - (long long)Ndim * Bdim;
    if (tail > 0)
        zero_kernel<<<1, 256>>>(out + (size_t)Ndim * Bdim, (size_t)tail);
}